// round 4
// baseline (speedup 1.0000x reference)
#include <cuda_runtime.h>

#define B_ 8192
#define T_ 128
#define DT_ 0.01f
#define THREADS 128
#define ROWS 16
#define NBLK (B_ / ROWS)

// shared memory layout (float offsets)
#define OFF_W1    0                      // [18][512]  (h<256: Wen1, h>=256: Wd1)
#define OFF_WEN2  9216                   // [256]
#define OFF_WD2T  9472                   // [6][256]   (transposed Wd2)
#define OFF_CS    11008                  // [16 rows][512]  per-row constant part
#define OFF_XS    19200                  // [2][18][16] double-buffered step inputs
#define OFF_PK    19776                  // [2][96]  kinetics partials (per warp-pair half)
#define OFF_PS    19968                  // [2][16]  stress partials
#define SMEM_FLOATS 20000
#define SMEM_BYTES (SMEM_FLOATS * 4)

typedef unsigned long long u64;

__device__ __forceinline__ u64 ffma2(u64 a, u64 b, u64 c) {
    u64 d; asm("fma.rn.f32x2 %0, %1, %2, %3;" : "=l"(d) : "l"(a), "l"(b), "l"(c));
    return d;
}
__device__ __forceinline__ u64 dup2(float x) {
    u64 d; asm("mov.b64 %0, {%1, %1};" : "=l"(d) : "f"(x));
    return d;
}
__device__ __forceinline__ float2 unpk(u64 a) {
    float2 r; asm("mov.b64 {%0, %1}, %2;" : "=f"(r.x), "=f"(r.y) : "l"(a));
    return r;
}
__device__ __forceinline__ u64 pk2(float x, float y) {
    u64 d; asm("mov.b64 %0, {%1, %2};" : "=l"(d) : "f"(x), "f"(y));
    return d;
}
__device__ __forceinline__ u64 relu2(u64 a) {
    float2 v = unpk(a);
    return pk2(fmaxf(v.x, 0.f), fmaxf(v.y, 0.f));
}

// fold-distribute over 32 slots: lane i ends with full-warp sum of v[i] in v[0]
__device__ __forceinline__ void fold32(float* v, int lane) {
    #pragma unroll
    for (int lvl = 0; lvl < 5; lvl++) {
        const int off = 16 >> lvl;
        #pragma unroll
        for (int m = 0; m < (16 >> lvl); m++) {
            float send = (lane & off) ? v[m] : v[m + off];
            float recv = __shfl_xor_sync(0xffffffffu, send, off);
            float keep = (lane & off) ? v[m + off] : v[m];
            v[m] = keep + recv;
        }
    }
}

__global__ void __launch_bounds__(THREADS, 2) visco_kernel(
    const float* __restrict__ e_,   const float* __restrict__ ed_,
    const float* __restrict__ E_,   const float* __restrict__ nu_,
    const float* __restrict__ We,   const float* __restrict__ be,
    const float* __restrict__ Wn,   const float* __restrict__ bn,
    const float* __restrict__ Wen1, const float* __restrict__ ben1,
    const float* __restrict__ Wen2, const float* __restrict__ ben2,
    const float* __restrict__ Wd1,  const float* __restrict__ bd1,
    const float* __restrict__ Wd2,  const float* __restrict__ bd2,
    float* __restrict__ out)
{
    extern __shared__ float sm[];
    float* W1s   = sm + OFF_W1;
    float* Wen2s = sm + OFF_WEN2;
    float* Wd2t  = sm + OFF_WD2T;
    float* cs    = sm + OFF_CS;
    float* xs    = sm + OFF_XS;
    float* pk    = sm + OFF_PK;
    float* ps    = sm + OFF_PS;

    const int tid  = threadIdx.x;
    const int lane = tid & 31;
    const int warp = tid >> 5;
    const int row0 = blockIdx.x * ROWS;

    // ---- cooperative smem fill: combined W1 + layer-2 weights ----
    for (int i = tid; i < 18 * 512; i += THREADS) {
        int k = i >> 9, h = i & 511;
        W1s[i] = (h < 256) ? Wen1[k * 256 + h] : Wd1[k * 256 + (h - 256)];
    }
    for (int i = tid; i < 256; i += THREADS) Wen2s[i] = Wen2[i];
    for (int i = tid; i < 6 * 256; i += THREADS) {
        int j = i >> 8, h = i & 255;
        Wd2t[i] = Wd2[h * 6 + j];
    }

    // ---- per-row constant part cs[r][h] = b1[h] + mf(32) @ W1[18:50][h] ----
    // thread owns hidden h0..h0+3; process rows in chunks of 4
    {
        const int h0 = 4 * tid;
        const float* bsrc  = (h0 < 256) ? (ben1 + h0) : (bd1 + h0 - 256);
        const float* Wbase = (h0 < 256) ? (Wen1 + 18 * 256 + h0)
                                        : (Wd1  + 18 * 256 + h0 - 256);
        const float b0 = bsrc[0], b1v = bsrc[1], b2v = bsrc[2], b3v = bsrc[3];
        for (int rc = 0; rc < 4; rc++) {
            float E4[4], nu4[4];
            #pragma unroll
            for (int rr = 0; rr < 4; rr++) {
                E4[rr]  = E_[row0 + rc * 4 + rr];
                nu4[rr] = nu_[row0 + rc * 4 + rr];
            }
            float c0[4], c1[4], c2[4], c3[4];
            #pragma unroll
            for (int rr = 0; rr < 4; rr++) { c0[rr]=b0; c1[rr]=b1v; c2[rr]=b2v; c3[rr]=b3v; }
            for (int k = 0; k < 32; k++) {
                float w, b;
                if (k < 16) { w = We[k];      b = be[k]; }
                else        { w = Wn[k - 16]; b = bn[k - 16]; }
                float4 w4 = *(const float4*)(Wbase + k * 256);
                #pragma unroll
                for (int rr = 0; rr < 4; rr++) {
                    float m = fmaf((k < 16) ? E4[rr] : nu4[rr], w, b);
                    c0[rr] = fmaf(m, w4.x, c0[rr]);
                    c1[rr] = fmaf(m, w4.y, c1[rr]);
                    c2[rr] = fmaf(m, w4.z, c2[rr]);
                    c3[rr] = fmaf(m, w4.w, c3[rr]);
                }
            }
            #pragma unroll
            for (int rr = 0; rr < 4; rr++)
                *(float4*)(cs + (rc * 4 + rr) * 512 + h0)
                    = make_float4(c0[rr], c1[rr], c2[rr], c3[rr]);
        }
    }

    // ---- init xs[0]: e/ed at t=0, xi = 0 ----
    const int jown = tid % 6;        // valid for tid < 96
    const int rown = tid / 6;
    if (tid < 96) {
        xs[jown * 16 + rown]        = e_[(row0 + rown) * T_ * 6 + jown];
        xs[(6 + jown) * 16 + rown]  = ed_[(row0 + rown) * T_ * 6 + jown];
        xs[(12 + jown) * 16 + rown] = 0.f;
    }
    __syncthreads();

    // ---- per-thread loop-invariant state ----
    float xi_val = 0.f;
    const float bd2v  = (tid < 96) ? bd2[jown] : 0.f;
    const float ben2r = ben2[0];
    float* xi_ptr = out + B_ * T_ + ((row0 + rown) * T_) * 6 + jown;  // tid<96
    const int so = tid - 96;                                         // stress owner 0..15
    float* s_ptr  = out + (row0 + (so & 15)) * T_;

    const float* W1w = W1s + 128 * warp + 4 * lane;   // + k*512
    const float* csw = cs  + 128 * warp + 4 * lane;   // + r*512

    // layer-2 weights in registers (warp-dependent slice)
    ulonglong2 wen2x;
    ulonglong2 wd2x[6];
    if (warp < 2) {
        wen2x = *(const ulonglong2*)(Wen2s + 128 * warp + 4 * lane);
    } else {
        #pragma unroll
        for (int j = 0; j < 6; j++)
            wd2x[j] = *(const ulonglong2*)(Wd2t + j * 256 + 128 * (warp - 2) + 4 * lane);
    }

    for (int t = 0; t < T_; t++) {
        const int p = t & 1;
        const float* xsp = xs + p * 288;
        float* xsn = xs + (p ^ 1) * 288;

        // prefetch e/ed for t+1 (latency hidden under the k-loop)
        float pe = 0.f, ped = 0.f;
        if (tid < 96) {
            int tn = (t + 1 < T_) ? (t + 1) : (T_ - 1);
            pe  = e_[(row0 + rown) * T_ * 6 + tn * 6 + jown];
            ped = ed_[(row0 + rown) * T_ * 6 + tn * 6 + jown];
        }

        // ---- layer 1: 18 inputs x (this warp's 128 hidden) x 16 rows ----
        u64 u2[16][2];
        #pragma unroll
        for (int r = 0; r < 16; r++) {
            ulonglong2 c = *(const ulonglong2*)(csw + r * 512);
            u2[r][0] = c.x; u2[r][1] = c.y;
        }
        #pragma unroll
        for (int k = 0; k < 18; k++) {
            ulonglong2 w = *(const ulonglong2*)(W1w + k * 512);
            #pragma unroll
            for (int m = 0; m < 4; m++) {
                float4 xv = *(const float4*)(xsp + k * 16 + 4 * m);  // broadcast
                u64 x0 = dup2(xv.x), x1 = dup2(xv.y), x2 = dup2(xv.z), x3 = dup2(xv.w);
                u2[4*m+0][0] = ffma2(x0, w.x, u2[4*m+0][0]);
                u2[4*m+0][1] = ffma2(x0, w.y, u2[4*m+0][1]);
                u2[4*m+1][0] = ffma2(x1, w.x, u2[4*m+1][0]);
                u2[4*m+1][1] = ffma2(x1, w.y, u2[4*m+1][1]);
                u2[4*m+2][0] = ffma2(x2, w.x, u2[4*m+2][0]);
                u2[4*m+2][1] = ffma2(x2, w.y, u2[4*m+2][1]);
                u2[4*m+3][0] = ffma2(x3, w.x, u2[4*m+3][0]);
                u2[4*m+3][1] = ffma2(x3, w.y, u2[4*m+3][1]);
            }
        }
        #pragma unroll
        for (int r = 0; r < 16; r++) {
            u2[r][0] = relu2(u2[r][0]);
            u2[r][1] = relu2(u2[r][1]);
        }

        // ---- layer 2 partials + in-warp fold + STS ----
        if (warp < 2) {
            // energy half: stress partial per row
            float v[32];
            #pragma unroll
            for (int r = 0; r < 16; r++) {
                u64 s2 = ffma2(u2[r][0], wen2x.x, 0ULL);
                s2 = ffma2(u2[r][1], wen2x.y, s2);
                float2 q = unpk(s2);
                v[r] = q.x + q.y;
            }
            #pragma unroll
            for (int r = 16; r < 32; r++) v[r] = 0.f;
            fold32(v, lane);
            if (lane < 16) ps[warp * 16 + lane] = v[0];
        } else {
            // kinetics half: 6 partials per row -> 96 slots, 3 fold trees
            float v0[32], v1[32], v2[32];
            #pragma unroll
            for (int r = 0; r < 16; r++) {
                #pragma unroll
                for (int j = 0; j < 6; j++) {
                    u64 a2 = ffma2(u2[r][0], wd2x[j].x, 0ULL);
                    a2 = ffma2(u2[r][1], wd2x[j].y, a2);
                    float2 q = unpk(a2);
                    int s = r * 6 + j;
                    float val = q.x + q.y;
                    if (s < 32)      v0[s]      = val;
                    else if (s < 64) v1[s - 32] = val;
                    else             v2[s - 64] = val;
                }
            }
            fold32(v0, lane);
            fold32(v1, lane);
            fold32(v2, lane);
            float* pkw = pk + (warp - 2) * 96;
            pkw[lane]      = v0[0];
            pkw[32 + lane] = v1[0];
            pkw[64 + lane] = v2[0];
        }

        // stage next step's e/ed while partials settle
        if (tid < 96) {
            xsn[jown * 16 + rown]       = pe;
            xsn[(6 + jown) * 16 + rown] = ped;
        }
        __syncthreads();

        // ---- owner combine: outputs + Euler update + xi into next buffer ----
        if (tid < 96) {
            float kin = pk[tid] + pk[96 + tid];
            xi_ptr[t * 6] = xi_val;                       // emit xi BEFORE update
            xi_val = fmaf(DT_, kin + bd2v, xi_val);
            xsn[(12 + jown) * 16 + rown] = xi_val;
        } else if (tid < 112) {
            s_ptr[t] = ps[so] + ps[16 + so] + ben2r;
        }
        __syncthreads();
    }
}

extern "C" void kernel_launch(void* const* d_in, const int* in_sizes, int n_in,
                              void* d_out, int out_size) {
    (void)in_sizes; (void)n_in; (void)out_size;
    cudaFuncSetAttribute(visco_kernel,
                         cudaFuncAttributeMaxDynamicSharedMemorySize, SMEM_BYTES);
    visco_kernel<<<NBLK, THREADS, SMEM_BYTES>>>(
        (const float*)d_in[0],  (const float*)d_in[1],
        (const float*)d_in[2],  (const float*)d_in[3],
        (const float*)d_in[4],  (const float*)d_in[5],
        (const float*)d_in[6],  (const float*)d_in[7],
        (const float*)d_in[8],  (const float*)d_in[9],
        (const float*)d_in[10], (const float*)d_in[11],
        (const float*)d_in[12], (const float*)d_in[13],
        (const float*)d_in[14], (const float*)d_in[15],
        (float*)d_out);
}

// round 5
// speedup vs baseline: 1.7978x; 1.7978x over previous
#include <cuda_runtime.h>

#define B_ 8192
#define T_ 128
#define DT_ 0.01f
#define THREADS 128
#define ROWS 16
#define NBLK (B_ / ROWS)

// shared memory layout (float offsets)
#define OFF_W1    0        // [18][512]  (h<256: Wen1, h>=256: Wd1)
#define OFF_WEN2  9216     // [256]
#define OFF_WD2T  9472     // [6][256]   (transposed Wd2)
#define OFF_CS    11008    // [16 rows][512]  per-row constant part
#define OFF_XS    19200    // [2 pairs][2 buf][18 k][8 rows][2 dup]
#define OFF_PP    20352    // [2 pairs][2 warps][56] partials
#define SMEM_FLOATS 20608
#define SMEM_BYTES (SMEM_FLOATS * 4)

typedef unsigned long long u64;

__device__ __forceinline__ u64 ffma2(u64 a, u64 b, u64 c) {
    u64 d; asm("fma.rn.f32x2 %0, %1, %2, %3;" : "=l"(d) : "l"(a), "l"(b), "l"(c));
    return d;
}
__device__ __forceinline__ u64 dup2(float x) {
    u64 d; asm("mov.b64 %0, {%1, %1};" : "=l"(d) : "f"(x));
    return d;
}
__device__ __forceinline__ float2 unpk(u64 a) {
    float2 r; asm("mov.b64 {%0, %1}, %2;" : "=f"(r.x), "=f"(r.y) : "l"(a));
    return r;
}
__device__ __forceinline__ u64 pk2(float x, float y) {
    u64 d; asm("mov.b64 %0, {%1, %2};" : "=l"(d) : "f"(x), "f"(y));
    return d;
}
__device__ __forceinline__ u64 relu2(u64 a) {
    float2 v = unpk(a);
    return pk2(fmaxf(v.x, 0.f), fmaxf(v.y, 0.f));
}
__device__ __forceinline__ void barpair(int id) {
    asm volatile("bar.sync %0, %1;" :: "r"(id), "r"(64) : "memory");
}

// fold-distribute over 32 slots: lane i ends with full-warp sum of v[i] in v[0]
__device__ __forceinline__ void fold32(float* v, int lane) {
    #pragma unroll
    for (int lvl = 0; lvl < 5; lvl++) {
        const int off = 16 >> lvl;
        #pragma unroll
        for (int m = 0; m < (16 >> lvl); m++) {
            float send = (lane & off) ? v[m] : v[m + off];
            float recv = __shfl_xor_sync(0xffffffffu, send, off);
            float keep = (lane & off) ? v[m + off] : v[m];
            v[m] = keep + recv;
        }
    }
}

__global__ void __launch_bounds__(THREADS, 2) visco_kernel(
    const float* __restrict__ e_,   const float* __restrict__ ed_,
    const float* __restrict__ E_,   const float* __restrict__ nu_,
    const float* __restrict__ We,   const float* __restrict__ be,
    const float* __restrict__ Wn,   const float* __restrict__ bn,
    const float* __restrict__ Wen1, const float* __restrict__ ben1,
    const float* __restrict__ Wen2, const float* __restrict__ ben2,
    const float* __restrict__ Wd1,  const float* __restrict__ bd1,
    const float* __restrict__ Wd2,  const float* __restrict__ bd2,
    float* __restrict__ out)
{
    extern __shared__ float sm[];
    float* W1s   = sm + OFF_W1;
    float* Wen2s = sm + OFF_WEN2;
    float* Wd2t  = sm + OFF_WD2T;
    float* cs    = sm + OFF_CS;

    const int tid  = threadIdx.x;
    const int lane = tid & 31;
    const int warp = tid >> 5;
    const int pairIdx = warp >> 1;     // 0,1
    const int pw      = warp & 1;      // warp-in-pair
    const int row0 = blockIdx.x * ROWS;

    float* xsP = sm + OFF_XS + pairIdx * 576;   // 2 buffers x 288
    float* pP  = sm + OFF_PP + pairIdx * 112;   // [2][56]

    // ---- cooperative smem fill: combined W1 + layer-2 weights ----
    for (int i = tid; i < 18 * 512; i += THREADS) {
        int k = i >> 9, h = i & 511;
        W1s[i] = (h < 256) ? Wen1[k * 256 + h] : Wd1[k * 256 + (h - 256)];
    }
    for (int i = tid; i < 256; i += THREADS) Wen2s[i] = Wen2[i];
    for (int i = tid; i < 6 * 256; i += THREADS) {
        int j = i >> 8, h = i & 255;
        Wd2t[i] = Wd2[h * 6 + j];
    }

    // ---- per-row constant part cs[r][h] = b1[h] + mf(32) @ W1[18:50][h] ----
    {
        const int h0 = 4 * tid;
        const float* bsrc  = (h0 < 256) ? (ben1 + h0) : (bd1 + h0 - 256);
        const float* Wbase = (h0 < 256) ? (Wen1 + 18 * 256 + h0)
                                        : (Wd1  + 18 * 256 + h0 - 256);
        const float b0 = bsrc[0], b1v = bsrc[1], b2v = bsrc[2], b3v = bsrc[3];
        for (int rc = 0; rc < 4; rc++) {
            float E4[4], nu4[4];
            #pragma unroll
            for (int rr = 0; rr < 4; rr++) {
                E4[rr]  = E_[row0 + rc * 4 + rr];
                nu4[rr] = nu_[row0 + rc * 4 + rr];
            }
            float c0[4], c1[4], c2[4], c3[4];
            #pragma unroll
            for (int rr = 0; rr < 4; rr++) { c0[rr]=b0; c1[rr]=b1v; c2[rr]=b2v; c3[rr]=b3v; }
            for (int k = 0; k < 32; k++) {
                float w, b;
                if (k < 16) { w = We[k];      b = be[k]; }
                else        { w = Wn[k - 16]; b = bn[k - 16]; }
                float4 w4 = *(const float4*)(Wbase + k * 256);
                #pragma unroll
                for (int rr = 0; rr < 4; rr++) {
                    float m = fmaf((k < 16) ? E4[rr] : nu4[rr], w, b);
                    c0[rr] = fmaf(m, w4.x, c0[rr]);
                    c1[rr] = fmaf(m, w4.y, c1[rr]);
                    c2[rr] = fmaf(m, w4.z, c2[rr]);
                    c3[rr] = fmaf(m, w4.w, c3[rr]);
                }
            }
            #pragma unroll
            for (int rr = 0; rr < 4; rr++)
                *(float4*)(cs + (rc * 4 + rr) * 512 + h0)
                    = make_float4(c0[rr], c1[rr], c2[rr], c3[rr]);
        }
    }

    // ---- per-thread roles ----
    const int pt = pw * 32 + lane;            // thread index within pair (0..63)
    // e/ed stagers: pt < 48: (j, r) = (pt%6, pt/6)
    const int sj = pt % 6, sr = pt / 6;
    const bool stager = (pt < 48);
    const int ebase = (row0 + pairIdx * 8 + sr) * T_ * 6 + sj;

    // owners: lane < 28: slot s = pw*28 + lane; r = s/7, j = s%7
    const int s_own = pw * 28 + lane;
    const bool owner = (lane < 28);
    const int ro = s_own / 7, jo = s_own % 7;
    const int rowg = row0 + pairIdx * 8 + ro;
    const float bd2v  = (owner && jo < 6) ? bd2[jo] : 0.f;
    const float ben2r = ben2[0];
    float xi_val = 0.f;
    float* xi_ptr = out + B_ * T_ + (rowg * T_) * 6 + jo;   // jo<6 owners
    float* s_ptr  = out + rowg * T_;                        // jo==6 owners

    // ---- initial xs fill (t=0): e/ed + xi=0, duplicated f32x2 ----
    if (stager) {
        float ev  = e_[ebase];
        float edv = ed_[ebase];
        *(u64*)(xsP + (sj * 8 + sr) * 2)        = dup2(ev);
        *(u64*)(xsP + ((6 + sj) * 8 + sr) * 2)  = dup2(edv);
        *(u64*)(xsP + ((12 + sj) * 8 + sr) * 2) = 0ULL;
    }
    __syncthreads();

    // ---- loop-invariant pointers / registers ----
    const float* W1wE = W1s + 128 * pw + 4 * lane;          // + k*512
    const float* W1wK = W1s + 256 + 128 * pw + 4 * lane;    // + k*512
    const float* cswE = cs + (pairIdx * 8) * 512 + 128 * pw + 4 * lane;
    const float* cswK = cswE + 256;

    const ulonglong2 wen2x = *(const ulonglong2*)(Wen2s + 128 * pw + 4 * lane);
    ulonglong2 wd2x[6];
    #pragma unroll
    for (int j = 0; j < 6; j++)
        wd2x[j] = *(const ulonglong2*)(Wd2t + j * 256 + 128 * pw + 4 * lane);

    const int barId = 1 + pairIdx;

    for (int t = 0; t < T_; t++) {
        const int p = t & 1;
        const float* xsp = xsP + p * 288;
        float* xsn = xsP + (p ^ 1) * 288;

        // prefetch e/ed for t+1 (hidden under the k-loop)
        float pe = 0.f, ped = 0.f;
        if (stager) {
            int tn = (t + 1 < T_) ? (t + 1) : (T_ - 1);
            pe  = e_[ebase + tn * 6];
            ped = ed_[ebase + tn * 6];
        }

        // ---- layer 1: 18 inputs x 256 hidden (this warp's slice) x 8 rows ----
        u64 u2[8][4];   // [row][energy0, energy1, kin0, kin1]
        #pragma unroll
        for (int r = 0; r < 8; r++) {
            ulonglong2 cE = *(const ulonglong2*)(cswE + r * 512);
            ulonglong2 cK = *(const ulonglong2*)(cswK + r * 512);
            u2[r][0] = cE.x; u2[r][1] = cE.y;
            u2[r][2] = cK.x; u2[r][3] = cK.y;
        }
        #pragma unroll
        for (int k = 0; k < 18; k++) {
            ulonglong2 wE = *(const ulonglong2*)(W1wE + k * 512);
            ulonglong2 wK = *(const ulonglong2*)(W1wK + k * 512);
            #pragma unroll
            for (int g = 0; g < 4; g++) {
                // rows 2g, 2g+1, each stored duplicated as f32x2 (broadcast load)
                ulonglong2 xp = *(const ulonglong2*)(xsp + (k * 8 + 2 * g) * 2);
                u2[2*g][0]   = ffma2(xp.x, wE.x, u2[2*g][0]);
                u2[2*g][1]   = ffma2(xp.x, wE.y, u2[2*g][1]);
                u2[2*g][2]   = ffma2(xp.x, wK.x, u2[2*g][2]);
                u2[2*g][3]   = ffma2(xp.x, wK.y, u2[2*g][3]);
                u2[2*g+1][0] = ffma2(xp.y, wE.x, u2[2*g+1][0]);
                u2[2*g+1][1] = ffma2(xp.y, wE.y, u2[2*g+1][1]);
                u2[2*g+1][2] = ffma2(xp.y, wK.x, u2[2*g+1][2]);
                u2[2*g+1][3] = ffma2(xp.y, wK.y, u2[2*g+1][3]);
            }
        }
        #pragma unroll
        for (int r = 0; r < 8; r++) {
            u2[r][0] = relu2(u2[r][0]); u2[r][1] = relu2(u2[r][1]);
            u2[r][2] = relu2(u2[r][2]); u2[r][3] = relu2(u2[r][3]);
        }

        // ---- layer-2 partials: two groups of 4 rows (28 slots each), fold, STS ----
        #pragma unroll
        for (int g2 = 0; g2 < 2; g2++) {
            float v[32];
            #pragma unroll
            for (int rr = 0; rr < 4; rr++) {
                const int r = 4 * g2 + rr;
                #pragma unroll
                for (int j = 0; j < 6; j++) {
                    u64 a2 = ffma2(u2[r][2], wd2x[j].x, 0ULL);
                    a2 = ffma2(u2[r][3], wd2x[j].y, a2);
                    float2 q = unpk(a2);
                    v[rr * 7 + j] = q.x + q.y;
                }
                u64 s2 = ffma2(u2[r][0], wen2x.x, 0ULL);
                s2 = ffma2(u2[r][1], wen2x.y, s2);
                float2 q = unpk(s2);
                v[rr * 7 + 6] = q.x + q.y;
            }
            #pragma unroll
            for (int m = 28; m < 32; m++) v[m] = 0.f;
            fold32(v, lane);
            if (lane < 28) pP[pw * 56 + g2 * 28 + lane] = v[0];
        }

        // stage next step's e/ed (disjoint from xi entries, read only next iter)
        if (stager) {
            *(u64*)(xsn + (sj * 8 + sr) * 2)       = dup2(pe);
            *(u64*)(xsn + ((6 + sj) * 8 + sr) * 2) = dup2(ped);
        }
        barpair(barId);

        // ---- owner combine: outputs + Euler + xi into next buffer ----
        if (owner) {
            float val = pP[s_own] + pP[56 + s_own];
            if (jo < 6) {
                xi_ptr[t * 6] = xi_val;                  // emit xi BEFORE update
                xi_val = fmaf(DT_, val + bd2v, xi_val);
                *(u64*)(xsn + ((12 + jo) * 8 + ro) * 2) = dup2(xi_val);
            } else {
                s_ptr[t] = val + ben2r;
            }
        }
        barpair(barId);
    }
}

extern "C" void kernel_launch(void* const* d_in, const int* in_sizes, int n_in,
                              void* d_out, int out_size) {
    (void)in_sizes; (void)n_in; (void)out_size;
    cudaFuncSetAttribute(visco_kernel,
                         cudaFuncAttributeMaxDynamicSharedMemorySize, SMEM_BYTES);
    visco_kernel<<<NBLK, THREADS, SMEM_BYTES>>>(
        (const float*)d_in[0],  (const float*)d_in[1],
        (const float*)d_in[2],  (const float*)d_in[3],
        (const float*)d_in[4],  (const float*)d_in[5],
        (const float*)d_in[6],  (const float*)d_in[7],
        (const float*)d_in[8],  (const float*)d_in[9],
        (const float*)d_in[10], (const float*)d_in[11],
        (const float*)d_in[12], (const float*)d_in[13],
        (const float*)d_in[14], (const float*)d_in[15],
        (float*)d_out);
}

// round 6
// speedup vs baseline: 1.8470x; 1.0273x over previous
#include <cuda_runtime.h>

#define B_ 8192
#define T_ 128
#define DT_ 0.01f
#define THREADS 128
#define ROWS 16
#define NBLK (B_ / ROWS)

// shared memory layout (float offsets)
#define OFF_W1    0        // [18][512]  (h<256: Wen1, h>=256: Wd1)
#define OFF_CS    9216     // [16 rows][512]  per-row constant part
#define OFF_XS    17408    // [2 pairs][2 buf][18 k][8 rows][2 dup]
#define OFF_PP    18560    // [2 pairs][2 warps][56] partials
#define SMEM_FLOATS 18784
#define SMEM_BYTES (SMEM_FLOATS * 4)

typedef unsigned long long u64;

__device__ __forceinline__ u64 ffma2(u64 a, u64 b, u64 c) {
    u64 d; asm("fma.rn.f32x2 %0, %1, %2, %3;" : "=l"(d) : "l"(a), "l"(b), "l"(c));
    return d;
}
__device__ __forceinline__ u64 dup2(float x) {
    u64 d; asm("mov.b64 %0, {%1, %1};" : "=l"(d) : "f"(x));
    return d;
}
__device__ __forceinline__ float2 unpk(u64 a) {
    float2 r; asm("mov.b64 {%0, %1}, %2;" : "=f"(r.x), "=f"(r.y) : "l"(a));
    return r;
}
__device__ __forceinline__ u64 pk2(float x, float y) {
    u64 d; asm("mov.b64 %0, {%1, %2};" : "=l"(d) : "f"(x), "f"(y));
    return d;
}
__device__ __forceinline__ u64 relu2(u64 a) {
    float2 v = unpk(a);
    return pk2(fmaxf(v.x, 0.f), fmaxf(v.y, 0.f));
}
__device__ __forceinline__ void barpair(int id) {
    asm volatile("bar.sync %0, %1;" :: "r"(id), "r"(64) : "memory");
}

// fold-distribute over 32 slots: lane i ends with full-warp sum of v[i] in v[0]
__device__ __forceinline__ void fold32(float* v, int lane) {
    #pragma unroll
    for (int lvl = 0; lvl < 5; lvl++) {
        const int off = 16 >> lvl;
        #pragma unroll
        for (int m = 0; m < (16 >> lvl); m++) {
            float send = (lane & off) ? v[m] : v[m + off];
            float recv = __shfl_xor_sync(0xffffffffu, send, off);
            float keep = (lane & off) ? v[m + off] : v[m];
            v[m] = keep + recv;
        }
    }
}

__global__ void __launch_bounds__(THREADS, 3) visco_kernel(
    const float* __restrict__ e_,   const float* __restrict__ ed_,
    const float* __restrict__ E_,   const float* __restrict__ nu_,
    const float* __restrict__ We,   const float* __restrict__ be,
    const float* __restrict__ Wn,   const float* __restrict__ bn,
    const float* __restrict__ Wen1, const float* __restrict__ ben1,
    const float* __restrict__ Wen2, const float* __restrict__ ben2,
    const float* __restrict__ Wd1,  const float* __restrict__ bd1,
    const float* __restrict__ Wd2,  const float* __restrict__ bd2,
    float* __restrict__ out)
{
    extern __shared__ float sm[];
    float* W1s = sm + OFF_W1;
    float* cs  = sm + OFF_CS;

    const int tid  = threadIdx.x;
    const int lane = tid & 31;
    const int warp = tid >> 5;
    const int pairIdx = warp >> 1;     // 0,1
    const int pw      = warp & 1;      // warp-in-pair
    const int row0 = blockIdx.x * ROWS;

    float* xsP = sm + OFF_XS + pairIdx * 576;   // 2 buffers x 288
    float* pP  = sm + OFF_PP + pairIdx * 112;   // [2][56]

    // ---- cooperative smem fill: combined W1 only ----
    for (int i = tid; i < 18 * 512; i += THREADS) {
        int k = i >> 9, h = i & 511;
        W1s[i] = (h < 256) ? Wen1[k * 256 + h] : Wd1[k * 256 + (h - 256)];
    }

    // ---- per-row constant part cs[r][h] = b1[h] + mf(32) @ W1[18:50][h] ----
    {
        const int h0 = 4 * tid;
        const float* bsrc  = (h0 < 256) ? (ben1 + h0) : (bd1 + h0 - 256);
        const float* Wbase = (h0 < 256) ? (Wen1 + 18 * 256 + h0)
                                        : (Wd1  + 18 * 256 + h0 - 256);
        const float b0 = bsrc[0], b1v = bsrc[1], b2v = bsrc[2], b3v = bsrc[3];
        for (int rc = 0; rc < 4; rc++) {
            float E4[4], nu4[4];
            #pragma unroll
            for (int rr = 0; rr < 4; rr++) {
                E4[rr]  = E_[row0 + rc * 4 + rr];
                nu4[rr] = nu_[row0 + rc * 4 + rr];
            }
            float c0[4], c1[4], c2[4], c3[4];
            #pragma unroll
            for (int rr = 0; rr < 4; rr++) { c0[rr]=b0; c1[rr]=b1v; c2[rr]=b2v; c3[rr]=b3v; }
            for (int k = 0; k < 32; k++) {
                float w, b;
                if (k < 16) { w = We[k];      b = be[k]; }
                else        { w = Wn[k - 16]; b = bn[k - 16]; }
                float4 w4 = *(const float4*)(Wbase + k * 256);
                #pragma unroll
                for (int rr = 0; rr < 4; rr++) {
                    float m = fmaf((k < 16) ? E4[rr] : nu4[rr], w, b);
                    c0[rr] = fmaf(m, w4.x, c0[rr]);
                    c1[rr] = fmaf(m, w4.y, c1[rr]);
                    c2[rr] = fmaf(m, w4.z, c2[rr]);
                    c3[rr] = fmaf(m, w4.w, c3[rr]);
                }
            }
            #pragma unroll
            for (int rr = 0; rr < 4; rr++)
                *(float4*)(cs + (rc * 4 + rr) * 512 + h0)
                    = make_float4(c0[rr], c1[rr], c2[rr], c3[rr]);
        }
    }

    // ---- per-thread roles ----
    const int pt = pw * 32 + lane;            // thread index within pair (0..63)
    const int sj = pt % 6, sr = pt / 6;       // e/ed stagers (pt < 48)
    const bool stager = (pt < 48);
    const int ebase = (row0 + pairIdx * 8 + sr) * T_ * 6 + sj;

    // owners: lane < 28: slot s = pw*28 + lane; r = s/7, j = s%7
    const int s_own = pw * 28 + lane;
    const bool owner = (lane < 28);
    const int ro = s_own / 7, jo = s_own % 7;
    const int rowg = row0 + pairIdx * 8 + ro;
    const float bd2v  = (owner && jo < 6) ? bd2[jo] : 0.f;
    const float ben2r = ben2[0];
    float xi_val = 0.f;
    float* xi_ptr = out + B_ * T_ + (rowg * T_) * 6 + jo;   // jo<6 owners
    float* s_ptr  = out + rowg * T_;                        // jo==6 owners

    // ---- initial xs fill (t=0): e/ed + xi=0, duplicated f32x2 ----
    if (stager) {
        float ev  = e_[ebase];
        float edv = ed_[ebase];
        *(u64*)(xsP + (sj * 8 + sr) * 2)        = dup2(ev);
        *(u64*)(xsP + ((6 + sj) * 8 + sr) * 2)  = dup2(edv);
        *(u64*)(xsP + ((12 + sj) * 8 + sr) * 2) = 0ULL;
    }

    // ---- layer-2 weights: straight from gmem into registers (one-time) ----
    const int h0l = 128 * pw + 4 * lane;
    ulonglong2 wen2x;
    {
        float4 w = *(const float4*)(Wen2 + h0l);
        wen2x.x = pk2(w.x, w.y); wen2x.y = pk2(w.z, w.w);
    }
    ulonglong2 wd2x[6];
    #pragma unroll
    for (int j = 0; j < 6; j++) {
        float a0 = Wd2[(h0l + 0) * 6 + j];
        float a1 = Wd2[(h0l + 1) * 6 + j];
        float a2 = Wd2[(h0l + 2) * 6 + j];
        float a3 = Wd2[(h0l + 3) * 6 + j];
        wd2x[j].x = pk2(a0, a1); wd2x[j].y = pk2(a2, a3);
    }
    __syncthreads();

    // ---- loop-invariant pointers ----
    const float* W1wE = W1s + 128 * pw + 4 * lane;          // + k*512
    const float* W1wK = W1s + 256 + 128 * pw + 4 * lane;    // + k*512
    const float* cswE = cs + (pairIdx * 8) * 512 + 128 * pw + 4 * lane;
    const float* cswK = cswE + 256;

    const int barId = 1 + pairIdx;

    for (int t = 0; t < T_; t++) {
        const int p = t & 1;
        const float* xsp = xsP + p * 288;
        float* xsn = xsP + (p ^ 1) * 288;

        // prefetch e/ed for t+1 (hidden under the k-loop)
        float pe = 0.f, ped = 0.f;
        if (stager) {
            int tn = (t + 1 < T_) ? (t + 1) : (T_ - 1);
            pe  = e_[ebase + tn * 6];
            ped = ed_[ebase + tn * 6];
        }

        // ---- layer 1: 18 inputs x 256 hidden (this warp's slice) x 8 rows ----
        u64 u2[8][4];   // [row][energy0, energy1, kin0, kin1]
        #pragma unroll
        for (int r = 0; r < 8; r++) {
            ulonglong2 cE = *(const ulonglong2*)(cswE + r * 512);
            ulonglong2 cK = *(const ulonglong2*)(cswK + r * 512);
            u2[r][0] = cE.x; u2[r][1] = cE.y;
            u2[r][2] = cK.x; u2[r][3] = cK.y;
        }
        #pragma unroll
        for (int k = 0; k < 18; k++) {
            ulonglong2 wE = *(const ulonglong2*)(W1wE + k * 512);
            ulonglong2 wK = *(const ulonglong2*)(W1wK + k * 512);
            #pragma unroll
            for (int g = 0; g < 4; g++) {
                ulonglong2 xp = *(const ulonglong2*)(xsp + (k * 8 + 2 * g) * 2);
                u2[2*g][0]   = ffma2(xp.x, wE.x, u2[2*g][0]);
                u2[2*g][1]   = ffma2(xp.x, wE.y, u2[2*g][1]);
                u2[2*g][2]   = ffma2(xp.x, wK.x, u2[2*g][2]);
                u2[2*g][3]   = ffma2(xp.x, wK.y, u2[2*g][3]);
                u2[2*g+1][0] = ffma2(xp.y, wE.x, u2[2*g+1][0]);
                u2[2*g+1][1] = ffma2(xp.y, wE.y, u2[2*g+1][1]);
                u2[2*g+1][2] = ffma2(xp.y, wK.x, u2[2*g+1][2]);
                u2[2*g+1][3] = ffma2(xp.y, wK.y, u2[2*g+1][3]);
            }
        }
        #pragma unroll
        for (int r = 0; r < 8; r++) {
            u2[r][0] = relu2(u2[r][0]); u2[r][1] = relu2(u2[r][1]);
            u2[r][2] = relu2(u2[r][2]); u2[r][3] = relu2(u2[r][3]);
        }

        // ---- layer-2 partials: two groups of 4 rows (28 slots each), fold, STS ----
        #pragma unroll
        for (int g2 = 0; g2 < 2; g2++) {
            float v[32];
            #pragma unroll
            for (int rr = 0; rr < 4; rr++) {
                const int r = 4 * g2 + rr;
                #pragma unroll
                for (int j = 0; j < 6; j++) {
                    u64 a2 = ffma2(u2[r][2], wd2x[j].x, 0ULL);
                    a2 = ffma2(u2[r][3], wd2x[j].y, a2);
                    float2 q = unpk(a2);
                    v[rr * 7 + j] = q.x + q.y;
                }
                u64 s2 = ffma2(u2[r][0], wen2x.x, 0ULL);
                s2 = ffma2(u2[r][1], wen2x.y, s2);
                float2 q = unpk(s2);
                v[rr * 7 + 6] = q.x + q.y;
            }
            #pragma unroll
            for (int m = 28; m < 32; m++) v[m] = 0.f;
            fold32(v, lane);
            if (lane < 28) pP[pw * 56 + g2 * 28 + lane] = v[0];
        }

        // stage next step's e/ed (disjoint from xi entries, read only next iter)
        if (stager) {
            *(u64*)(xsn + (sj * 8 + sr) * 2)       = dup2(pe);
            *(u64*)(xsn + ((6 + sj) * 8 + sr) * 2) = dup2(ped);
        }
        barpair(barId);

        // ---- owner combine: outputs + Euler + xi into next buffer ----
        if (owner) {
            float val = pP[s_own] + pP[56 + s_own];
            if (jo < 6) {
                xi_ptr[t * 6] = xi_val;                  // emit xi BEFORE update
                xi_val = fmaf(DT_, val + bd2v, xi_val);
                *(u64*)(xsn + ((12 + jo) * 8 + ro) * 2) = dup2(xi_val);
            } else {
                s_ptr[t] = val + ben2r;
            }
        }
        barpair(barId);
    }
}

extern "C" void kernel_launch(void* const* d_in, const int* in_sizes, int n_in,
                              void* d_out, int out_size) {
    (void)in_sizes; (void)n_in; (void)out_size;
    cudaFuncSetAttribute(visco_kernel,
                         cudaFuncAttributeMaxDynamicSharedMemorySize, SMEM_BYTES);
    visco_kernel<<<NBLK, THREADS, SMEM_BYTES>>>(
        (const float*)d_in[0],  (const float*)d_in[1],
        (const float*)d_in[2],  (const float*)d_in[3],
        (const float*)d_in[4],  (const float*)d_in[5],
        (const float*)d_in[6],  (const float*)d_in[7],
        (const float*)d_in[8],  (const float*)d_in[9],
        (const float*)d_in[10], (const float*)d_in[11],
        (const float*)d_in[12], (const float*)d_in[13],
        (const float*)d_in[14], (const float*)d_in[15],
        (float*)d_out);
}

// round 7
// speedup vs baseline: 1.8491x; 1.0011x over previous
#include <cuda_runtime.h>

#define B_ 8192
#define T_ 128
#define DT_ 0.01f
#define THREADS 128
#define ROWS 16
#define NBLK (B_ / ROWS)

// shared memory layout (float offsets)
#define OFF_W1    0        // [18][512]  (h<256: Wen1, h>=256: Wd1)
#define OFF_CS    9216     // [16 rows][512]  per-row constant part
#define OFF_XS    17408    // [2 pairs][2 buf][18 k][8 rows][2 dup]
#define OFF_PP    18560    // [2 pairs][2 warps][56] partials
#define SMEM_FLOATS 18784
#define SMEM_BYTES (SMEM_FLOATS * 4)

typedef unsigned long long u64;

__device__ __forceinline__ u64 ffma2(u64 a, u64 b, u64 c) {
    u64 d; asm("fma.rn.f32x2 %0, %1, %2, %3;" : "=l"(d) : "l"(a), "l"(b), "l"(c));
    return d;
}
__device__ __forceinline__ u64 dup2(float x) {
    u64 d; asm("mov.b64 %0, {%1, %1};" : "=l"(d) : "f"(x));
    return d;
}
__device__ __forceinline__ float2 unpk(u64 a) {
    float2 r; asm("mov.b64 {%0, %1}, %2;" : "=f"(r.x), "=f"(r.y) : "l"(a));
    return r;
}
__device__ __forceinline__ u64 pk2(float x, float y) {
    u64 d; asm("mov.b64 %0, {%1, %2};" : "=l"(d) : "f"(x), "f"(y));
    return d;
}
__device__ __forceinline__ u64 relu2(u64 a) {
    float2 v = unpk(a);
    return pk2(fmaxf(v.x, 0.f), fmaxf(v.y, 0.f));
}
__device__ __forceinline__ void barpair(int id) {
    asm volatile("bar.sync %0, %1;" :: "r"(id), "r"(64) : "memory");
}

// fold-distribute over 32 slots: lane i ends with full-warp sum of v[i] in v[0]
__device__ __forceinline__ void fold32(float* v, int lane) {
    #pragma unroll
    for (int lvl = 0; lvl < 5; lvl++) {
        const int off = 16 >> lvl;
        #pragma unroll
        for (int m = 0; m < (16 >> lvl); m++) {
            float send = (lane & off) ? v[m] : v[m + off];
            float recv = __shfl_xor_sync(0xffffffffu, send, off);
            float keep = (lane & off) ? v[m + off] : v[m];
            v[m] = keep + recv;
        }
    }
}

__global__ void __launch_bounds__(THREADS, 3) visco_kernel(
    const float* __restrict__ e_,   const float* __restrict__ ed_,
    const float* __restrict__ E_,   const float* __restrict__ nu_,
    const float* __restrict__ We,   const float* __restrict__ be,
    const float* __restrict__ Wn,   const float* __restrict__ bn,
    const float* __restrict__ Wen1, const float* __restrict__ ben1,
    const float* __restrict__ Wen2, const float* __restrict__ ben2,
    const float* __restrict__ Wd1,  const float* __restrict__ bd1,
    const float* __restrict__ Wd2,  const float* __restrict__ bd2,
    float* __restrict__ out)
{
    extern __shared__ float sm[];
    float* W1s = sm + OFF_W1;
    float* cs  = sm + OFF_CS;

    const int tid  = threadIdx.x;
    const int lane = tid & 31;
    const int warp = tid >> 5;
    const int pairIdx = warp >> 1;     // 0,1
    const int pw      = warp & 1;      // warp-in-pair
    const int row0 = blockIdx.x * ROWS;

    float* xsP = sm + OFF_XS + pairIdx * 576;   // 2 buffers x 288
    float* pP  = sm + OFF_PP + pairIdx * 112;   // [2][56]

    // ---- cooperative smem fill: combined W1 only ----
    for (int i = tid; i < 18 * 512; i += THREADS) {
        int k = i >> 9, h = i & 511;
        W1s[i] = (h < 256) ? Wen1[k * 256 + h] : Wd1[k * 256 + (h - 256)];
    }

    // ---- per-row constant part cs[r][h] = b1[h] + mf(32) @ W1[18:50][h] ----
    {
        const int h0 = 4 * tid;
        const float* bsrc  = (h0 < 256) ? (ben1 + h0) : (bd1 + h0 - 256);
        const float* Wbase = (h0 < 256) ? (Wen1 + 18 * 256 + h0)
                                        : (Wd1  + 18 * 256 + h0 - 256);
        const float b0 = bsrc[0], b1v = bsrc[1], b2v = bsrc[2], b3v = bsrc[3];
        for (int rc = 0; rc < 4; rc++) {
            float E4[4], nu4[4];
            #pragma unroll
            for (int rr = 0; rr < 4; rr++) {
                E4[rr]  = E_[row0 + rc * 4 + rr];
                nu4[rr] = nu_[row0 + rc * 4 + rr];
            }
            float c0[4], c1[4], c2[4], c3[4];
            #pragma unroll
            for (int rr = 0; rr < 4; rr++) { c0[rr]=b0; c1[rr]=b1v; c2[rr]=b2v; c3[rr]=b3v; }
            for (int k = 0; k < 32; k++) {
                float w, b;
                if (k < 16) { w = We[k];      b = be[k]; }
                else        { w = Wn[k - 16]; b = bn[k - 16]; }
                float4 w4 = *(const float4*)(Wbase + k * 256);
                #pragma unroll
                for (int rr = 0; rr < 4; rr++) {
                    float m = fmaf((k < 16) ? E4[rr] : nu4[rr], w, b);
                    c0[rr] = fmaf(m, w4.x, c0[rr]);
                    c1[rr] = fmaf(m, w4.y, c1[rr]);
                    c2[rr] = fmaf(m, w4.z, c2[rr]);
                    c3[rr] = fmaf(m, w4.w, c3[rr]);
                }
            }
            #pragma unroll
            for (int rr = 0; rr < 4; rr++)
                *(float4*)(cs + (rc * 4 + rr) * 512 + h0)
                    = make_float4(c0[rr], c1[rr], c2[rr], c3[rr]);
        }
    }

    // ---- per-thread roles ----
    const int pt = pw * 32 + lane;            // thread index within pair (0..63)
    const int sj = pt % 6, sr = pt / 6;       // e/ed stagers (pt < 48)
    const bool stager = (pt < 48);
    const int ebase = (row0 + pairIdx * 8 + sr) * T_ * 6 + sj;

    // owners: lane < 28: slot s = pw*28 + lane; r = s/7, j = s%7
    const int s_own = pw * 28 + lane;
    const bool owner = (lane < 28);
    const int ro = s_own / 7, jo = s_own % 7;
    const int rowg = row0 + pairIdx * 8 + ro;
    const float bd2v  = (owner && jo < 6) ? bd2[jo] : 0.f;
    const float ben2r = ben2[0];
    float xi_val = 0.f;
    float* xi_ptr = out + B_ * T_ + (rowg * T_) * 6 + jo;   // jo<6 owners
    float* s_ptr  = out + rowg * T_;                        // jo==6 owners

    // ---- initial xs fill (t=0): e/ed + xi=0, duplicated f32x2 ----
    if (stager) {
        float ev  = e_[ebase];
        float edv = ed_[ebase];
        *(u64*)(xsP + (sj * 8 + sr) * 2)        = dup2(ev);
        *(u64*)(xsP + ((6 + sj) * 8 + sr) * 2)  = dup2(edv);
        *(u64*)(xsP + ((12 + sj) * 8 + sr) * 2) = 0ULL;
    }

    // ---- layer-2 weights: straight from gmem into registers (one-time) ----
    const int h0l = 128 * pw + 4 * lane;
    ulonglong2 wen2x;
    {
        float4 w = *(const float4*)(Wen2 + h0l);
        wen2x.x = pk2(w.x, w.y); wen2x.y = pk2(w.z, w.w);
    }
    ulonglong2 wd2x[6];
    #pragma unroll
    for (int j = 0; j < 6; j++) {
        float a0 = Wd2[(h0l + 0) * 6 + j];
        float a1 = Wd2[(h0l + 1) * 6 + j];
        float a2 = Wd2[(h0l + 2) * 6 + j];
        float a3 = Wd2[(h0l + 3) * 6 + j];
        wd2x[j].x = pk2(a0, a1); wd2x[j].y = pk2(a2, a3);
    }
    __syncthreads();

    // ---- loop-invariant pointers ----
    const float* W1wE = W1s + 128 * pw + 4 * lane;          // + k*512
    const float* W1wK = W1s + 256 + 128 * pw + 4 * lane;    // + k*512
    const float* cswE = cs + (pairIdx * 8) * 512 + 128 * pw + 4 * lane;
    const float* cswK = cswE + 256;

    const int barId = 1 + pairIdx;

    // prefetch e/ed for t=1
    float pe = 0.f, ped = 0.f;
    if (stager) { pe = e_[ebase + 6]; ped = ed_[ebase + 6]; }

    // ---- prologue: u2 = cs + k0..11 contributions for t=0 (xi not needed) ----
    u64 u2[8][4];   // [row][energy0, energy1, kin0, kin1]
    #pragma unroll
    for (int r = 0; r < 8; r++) {
        ulonglong2 cE = *(const ulonglong2*)(cswE + r * 512);
        ulonglong2 cK = *(const ulonglong2*)(cswK + r * 512);
        u2[r][0] = cE.x; u2[r][1] = cE.y;
        u2[r][2] = cK.x; u2[r][3] = cK.y;
    }
    #pragma unroll
    for (int k = 0; k < 12; k++) {
        ulonglong2 wE = *(const ulonglong2*)(W1wE + k * 512);
        ulonglong2 wK = *(const ulonglong2*)(W1wK + k * 512);
        #pragma unroll
        for (int g = 0; g < 4; g++) {
            ulonglong2 xp = *(const ulonglong2*)(xsP + (k * 8 + 2 * g) * 2);
            u2[2*g][0]   = ffma2(xp.x, wE.x, u2[2*g][0]);
            u2[2*g][1]   = ffma2(xp.x, wE.y, u2[2*g][1]);
            u2[2*g][2]   = ffma2(xp.x, wK.x, u2[2*g][2]);
            u2[2*g][3]   = ffma2(xp.x, wK.y, u2[2*g][3]);
            u2[2*g+1][0] = ffma2(xp.y, wE.x, u2[2*g+1][0]);
            u2[2*g+1][1] = ffma2(xp.y, wE.y, u2[2*g+1][1]);
            u2[2*g+1][2] = ffma2(xp.y, wK.x, u2[2*g+1][2]);
            u2[2*g+1][3] = ffma2(xp.y, wK.y, u2[2*g+1][3]);
        }
    }

    for (int t = 0; t < T_; t++) {
        const int p = t & 1;
        const float* xsp = xsP + p * 288;
        float* xsn = xsP + (p ^ 1) * 288;

        // ---- back half: xi inputs k=12..17 (xi(t) visible in xsp) ----
        #pragma unroll
        for (int k = 12; k < 18; k++) {
            ulonglong2 wE = *(const ulonglong2*)(W1wE + k * 512);
            ulonglong2 wK = *(const ulonglong2*)(W1wK + k * 512);
            #pragma unroll
            for (int g = 0; g < 4; g++) {
                ulonglong2 xp = *(const ulonglong2*)(xsp + (k * 8 + 2 * g) * 2);
                u2[2*g][0]   = ffma2(xp.x, wE.x, u2[2*g][0]);
                u2[2*g][1]   = ffma2(xp.x, wE.y, u2[2*g][1]);
                u2[2*g][2]   = ffma2(xp.x, wK.x, u2[2*g][2]);
                u2[2*g][3]   = ffma2(xp.x, wK.y, u2[2*g][3]);
                u2[2*g+1][0] = ffma2(xp.y, wE.x, u2[2*g+1][0]);
                u2[2*g+1][1] = ffma2(xp.y, wE.y, u2[2*g+1][1]);
                u2[2*g+1][2] = ffma2(xp.y, wK.x, u2[2*g+1][2]);
                u2[2*g+1][3] = ffma2(xp.y, wK.y, u2[2*g+1][3]);
            }
        }
        #pragma unroll
        for (int r = 0; r < 8; r++) {
            u2[r][0] = relu2(u2[r][0]); u2[r][1] = relu2(u2[r][1]);
            u2[r][2] = relu2(u2[r][2]); u2[r][3] = relu2(u2[r][3]);
        }

        // ---- layer-2 partials: two groups of 4 rows (28 slots each), fold, STS ----
        #pragma unroll
        for (int g2 = 0; g2 < 2; g2++) {
            float v[32];
            #pragma unroll
            for (int rr = 0; rr < 4; rr++) {
                const int r = 4 * g2 + rr;
                #pragma unroll
                for (int j = 0; j < 6; j++) {
                    u64 a2 = ffma2(u2[r][2], wd2x[j].x, 0ULL);
                    a2 = ffma2(u2[r][3], wd2x[j].y, a2);
                    float2 q = unpk(a2);
                    v[rr * 7 + j] = q.x + q.y;
                }
                u64 s2 = ffma2(u2[r][0], wen2x.x, 0ULL);
                s2 = ffma2(u2[r][1], wen2x.y, s2);
                float2 q = unpk(s2);
                v[rr * 7 + 6] = q.x + q.y;
            }
            #pragma unroll
            for (int m = 28; m < 32; m++) v[m] = 0.f;
            fold32(v, lane);
            if (lane < 28) pP[pw * 56 + g2 * 28 + lane] = v[0];
        }

        // stage e/ed(t+1) into next buffer; prefetch e/ed(t+2)
        if (stager) {
            *(u64*)(xsn + (sj * 8 + sr) * 2)       = dup2(pe);
            *(u64*)(xsn + ((6 + sj) * 8 + sr) * 2) = dup2(ped);
            int tn = (t + 2 < T_) ? (t + 2) : (T_ - 1);
            pe  = e_[ebase + tn * 6];
            ped = ed_[ebase + tn * 6];
        }
        barpair(barId);

        // ---- owner combine: outputs + Euler + xi(t+1) into next buffer ----
        if (owner) {
            float val = pP[s_own] + pP[56 + s_own];
            if (jo < 6) {
                xi_ptr[t * 6] = xi_val;                  // emit xi BEFORE update
                xi_val = fmaf(DT_, val + bd2v, xi_val);
                *(u64*)(xsn + ((12 + jo) * 8 + ro) * 2) = dup2(xi_val);
            } else {
                s_ptr[t] = val + ben2r;
            }
        }

        // ---- front half of t+1 (independent of xi(t+1)): cs init + k=0..11 ----
        #pragma unroll
        for (int r = 0; r < 8; r++) {
            ulonglong2 cE = *(const ulonglong2*)(cswE + r * 512);
            ulonglong2 cK = *(const ulonglong2*)(cswK + r * 512);
            u2[r][0] = cE.x; u2[r][1] = cE.y;
            u2[r][2] = cK.x; u2[r][3] = cK.y;
        }
        #pragma unroll
        for (int k = 0; k < 12; k++) {
            ulonglong2 wE = *(const ulonglong2*)(W1wE + k * 512);
            ulonglong2 wK = *(const ulonglong2*)(W1wK + k * 512);
            #pragma unroll
            for (int g = 0; g < 4; g++) {
                ulonglong2 xp = *(const ulonglong2*)(xsn + (k * 8 + 2 * g) * 2);
                u2[2*g][0]   = ffma2(xp.x, wE.x, u2[2*g][0]);
                u2[2*g][1]   = ffma2(xp.x, wE.y, u2[2*g][1]);
                u2[2*g][2]   = ffma2(xp.x, wK.x, u2[2*g][2]);
                u2[2*g][3]   = ffma2(xp.x, wK.y, u2[2*g][3]);
                u2[2*g+1][0] = ffma2(xp.y, wE.x, u2[2*g+1][0]);
                u2[2*g+1][1] = ffma2(xp.y, wE.y, u2[2*g+1][1]);
                u2[2*g+1][2] = ffma2(xp.y, wK.x, u2[2*g+1][2]);
                u2[2*g+1][3] = ffma2(xp.y, wK.y, u2[2*g+1][3]);
            }
        }
        barpair(barId);   // xi(t+1) now visible for next iteration's back half
    }
}

extern "C" void kernel_launch(void* const* d_in, const int* in_sizes, int n_in,
                              void* d_out, int out_size) {
    (void)in_sizes; (void)n_in; (void)out_size;
    cudaFuncSetAttribute(visco_kernel,
                         cudaFuncAttributeMaxDynamicSharedMemorySize, SMEM_BYTES);
    visco_kernel<<<NBLK, THREADS, SMEM_BYTES>>>(
        (const float*)d_in[0],  (const float*)d_in[1],
        (const float*)d_in[2],  (const float*)d_in[3],
        (const float*)d_in[4],  (const float*)d_in[5],
        (const float*)d_in[6],  (const float*)d_in[7],
        (const float*)d_in[8],  (const float*)d_in[9],
        (const float*)d_in[10], (const float*)d_in[11],
        (const float*)d_in[12], (const float*)d_in[13],
        (const float*)d_in[14], (const float*)d_in[15],
        (float*)d_out);
}

// round 8
// speedup vs baseline: 1.8735x; 1.0132x over previous
#include <cuda_runtime.h>

#define B_ 8192
#define T_ 128
#define DT_ 0.01f
#define THREADS 128
#define ROWS 16
#define NBLK (B_ / ROWS)

// shared memory layout (float offsets)
// W1s rows: 0..17 dynamic inputs (e6, ed6, xi6); 18 = beta (×E); 19 = gamma (×nu); 20 = alpha (init)
#define OFF_W1    0          // [21][512]
#define OFF_XS    10752      // [2 pairs][2 buf][21 k][8 rows][2 dup]
#define OFF_PP    12096      // [2 pairs][112] partials
#define SMEM_FLOATS 12320
#define SMEM_BYTES (SMEM_FLOATS * 4)

typedef unsigned long long u64;

__device__ __forceinline__ u64 ffma2(u64 a, u64 b, u64 c) {
    u64 d; asm("fma.rn.f32x2 %0, %1, %2, %3;" : "=l"(d) : "l"(a), "l"(b), "l"(c));
    return d;
}
__device__ __forceinline__ u64 dup2(float x) {
    u64 d; asm("mov.b64 %0, {%1, %1};" : "=l"(d) : "f"(x));
    return d;
}
__device__ __forceinline__ float2 unpk(u64 a) {
    float2 r; asm("mov.b64 {%0, %1}, %2;" : "=f"(r.x), "=f"(r.y) : "l"(a));
    return r;
}
__device__ __forceinline__ u64 pk2(float x, float y) {
    u64 d; asm("mov.b64 %0, {%1, %2};" : "=l"(d) : "f"(x), "f"(y));
    return d;
}
__device__ __forceinline__ u64 relu2(u64 a) {
    float2 v = unpk(a);
    return pk2(fmaxf(v.x, 0.f), fmaxf(v.y, 0.f));
}
__device__ __forceinline__ void barpair(int id) {
    asm volatile("bar.sync %0, %1;" :: "r"(id), "r"(64) : "memory");
}

// fold-distribute over 32 slots: lane i ends with full-warp sum of v[i] in v[0]
__device__ __forceinline__ void fold32(float* v, int lane) {
    #pragma unroll
    for (int lvl = 0; lvl < 5; lvl++) {
        const int off = 16 >> lvl;
        #pragma unroll
        for (int m = 0; m < (16 >> lvl); m++) {
            float send = (lane & off) ? v[m] : v[m + off];
            float recv = __shfl_xor_sync(0xffffffffu, send, off);
            float keep = (lane & off) ? v[m + off] : v[m];
            v[m] = keep + recv;
        }
    }
}

__global__ void __launch_bounds__(THREADS, 3) visco_kernel(
    const float* __restrict__ e_,   const float* __restrict__ ed_,
    const float* __restrict__ E_,   const float* __restrict__ nu_,
    const float* __restrict__ We,   const float* __restrict__ be,
    const float* __restrict__ Wn,   const float* __restrict__ bn,
    const float* __restrict__ Wen1, const float* __restrict__ ben1,
    const float* __restrict__ Wen2, const float* __restrict__ ben2,
    const float* __restrict__ Wd1,  const float* __restrict__ bd1,
    const float* __restrict__ Wd2,  const float* __restrict__ bd2,
    float* __restrict__ out)
{
    extern __shared__ float sm[];
    float* W1s = sm + OFF_W1;

    const int tid  = threadIdx.x;
    const int lane = tid & 31;
    const int warp = tid >> 5;
    const int pairIdx = warp >> 1;     // 0,1
    const int pw      = warp & 1;      // warp-in-pair
    const int row0 = blockIdx.x * ROWS;

    float* xsP = sm + OFF_XS + pairIdx * 672;   // 2 buffers x 336
    float* pP  = sm + OFF_PP + pairIdx * 112;   // [2][56]

    // ---- cooperative smem fill: dynamic W1 rows 0..17 ----
    for (int i = tid; i < 18 * 512; i += THREADS) {
        int k = i >> 9, h = i & 511;
        W1s[i] = (h < 256) ? Wen1[k * 256 + h] : Wd1[k * 256 + (h - 256)];
    }

    // ---- rows 18..20: beta = We@W1mf, gamma = Wn@W1mf, alpha = bias fold ----
    // mf = [E*We+be, nu*Wn+bn]  =>  c[h] = alpha[h] + E*beta[h] + nu*gamma[h]
    {
        const int h0 = 4 * tid;
        const float* bsrc = (h0 < 256) ? (ben1 + h0) : (bd1 + h0 - 256);
        const float* Wb   = (h0 < 256) ? (Wen1 + 18 * 256 + h0)
                                       : (Wd1  + 18 * 256 + h0 - 256);
        float al[4], bt[4], gm[4];
        #pragma unroll
        for (int el = 0; el < 4; el++) { al[el] = bsrc[el]; bt[el] = 0.f; gm[el] = 0.f; }
        for (int i = 0; i < 16; i++) {
            float4 wa = *(const float4*)(Wb + i * 256);          // row 18+i (E-encoder)
            float4 wb = *(const float4*)(Wb + (16 + i) * 256);   // row 34+i (nu-encoder)
            float wev = We[i], bev = be[i], wnv = Wn[i], bnv = bn[i];
            bt[0] = fmaf(wev, wa.x, bt[0]); bt[1] = fmaf(wev, wa.y, bt[1]);
            bt[2] = fmaf(wev, wa.z, bt[2]); bt[3] = fmaf(wev, wa.w, bt[3]);
            gm[0] = fmaf(wnv, wb.x, gm[0]); gm[1] = fmaf(wnv, wb.y, gm[1]);
            gm[2] = fmaf(wnv, wb.z, gm[2]); gm[3] = fmaf(wnv, wb.w, gm[3]);
            al[0] = fmaf(bev, wa.x, al[0]); al[1] = fmaf(bev, wa.y, al[1]);
            al[2] = fmaf(bev, wa.z, al[2]); al[3] = fmaf(bev, wa.w, al[3]);
            al[0] = fmaf(bnv, wb.x, al[0]); al[1] = fmaf(bnv, wb.y, al[1]);
            al[2] = fmaf(bnv, wb.z, al[2]); al[3] = fmaf(bnv, wb.w, al[3]);
        }
        *(float4*)(W1s + 18 * 512 + h0) = make_float4(bt[0], bt[1], bt[2], bt[3]);
        *(float4*)(W1s + 19 * 512 + h0) = make_float4(gm[0], gm[1], gm[2], gm[3]);
        *(float4*)(W1s + 20 * 512 + h0) = make_float4(al[0], al[1], al[2], al[3]);
    }

    // ---- per-thread roles ----
    const int pt = pw * 32 + lane;            // thread index within pair (0..63)
    const int sj = pt % 6, sr = pt / 6;       // e/ed stagers (pt < 48)
    const bool stager = (pt < 48);
    const int ebase = (row0 + pairIdx * 8 + sr) * T_ * 6 + sj;

    // owners: lane < 28: slot s = pw*28 + lane; r = s/7, j = s%7
    const int s_own = pw * 28 + lane;
    const bool owner = (lane < 28);
    const int ro = s_own / 7, jo = s_own % 7;
    const int rowg = row0 + pairIdx * 8 + ro;
    const float bd2v  = (owner && jo < 6) ? bd2[jo] : 0.f;
    const float ben2r = ben2[0];
    float xi_val = 0.f;
    float* xi_ptr = out + B_ * T_ + (rowg * T_) * 6 + jo;   // jo<6 owners
    float* s_ptr  = out + rowg * T_;                        // jo==6 owners

    // ---- initial xs fill: e/ed(t=0), xi=0 (buffer 0); E/nu static (both buffers) ----
    if (stager) {
        *(u64*)(xsP + (sj * 8 + sr) * 2)        = dup2(e_[ebase]);
        *(u64*)(xsP + ((6 + sj) * 8 + sr) * 2)  = dup2(ed_[ebase]);
        *(u64*)(xsP + ((12 + sj) * 8 + sr) * 2) = 0ULL;
    }
    if (pt < 16) {
        int rr = pt & 7;
        int kk = 18 + (pt >> 3);
        float val = (pt < 8) ? E_[row0 + pairIdx * 8 + rr]
                             : nu_[row0 + pairIdx * 8 + rr];
        u64 d = dup2(val);
        *(u64*)(xsP + (kk * 8 + rr) * 2)       = d;
        *(u64*)(xsP + 336 + (kk * 8 + rr) * 2) = d;
    }

    // ---- layer-2 weights: straight from gmem into registers (one-time) ----
    const int h0l = 128 * pw + 4 * lane;
    ulonglong2 wen2x;
    {
        float4 w = *(const float4*)(Wen2 + h0l);
        wen2x.x = pk2(w.x, w.y); wen2x.y = pk2(w.z, w.w);
    }
    ulonglong2 wd2x[6];
    #pragma unroll
    for (int j = 0; j < 6; j++) {
        float a0 = Wd2[(h0l + 0) * 6 + j];
        float a1 = Wd2[(h0l + 1) * 6 + j];
        float a2 = Wd2[(h0l + 2) * 6 + j];
        float a3 = Wd2[(h0l + 3) * 6 + j];
        wd2x[j].x = pk2(a0, a1); wd2x[j].y = pk2(a2, a3);
    }
    __syncthreads();

    // ---- loop-invariant pointers ----
    const float* W1wE = W1s + 128 * pw + 4 * lane;          // + k*512
    const float* W1wK = W1s + 256 + 128 * pw + 4 * lane;    // + k*512

    const int barId = 1 + pairIdx;

    // prefetch e/ed for t=1
    float pe = 0.f, ped = 0.f;
    if (stager) { pe = e_[ebase + 6]; ped = ed_[ebase + 6]; }

    u64 u2[8][4];   // [row][energy0, energy1, kin0, kin1]

    // front half: alpha init + k in {0..11, 18, 19} from given buffer
    #define FRONT_HALF(XBUF)                                                  \
    {                                                                         \
        ulonglong2 aE = *(const ulonglong2*)(W1wE + 20 * 512);                \
        ulonglong2 aK = *(const ulonglong2*)(W1wK + 20 * 512);                \
        _Pragma("unroll")                                                     \
        for (int r = 0; r < 8; r++) {                                         \
            u2[r][0] = aE.x; u2[r][1] = aE.y;                                 \
            u2[r][2] = aK.x; u2[r][3] = aK.y;                                 \
        }                                                                     \
        _Pragma("unroll")                                                     \
        for (int ki = 0; ki < 14; ki++) {                                     \
            const int k = (ki < 12) ? ki : (ki + 6);                          \
            ulonglong2 wE = *(const ulonglong2*)(W1wE + k * 512);             \
            ulonglong2 wK = *(const ulonglong2*)(W1wK + k * 512);             \
            _Pragma("unroll")                                                 \
            for (int g = 0; g < 4; g++) {                                     \
                ulonglong2 xp = *(const ulonglong2*)((XBUF) + (k * 8 + 2 * g) * 2); \
                u2[2*g][0]   = ffma2(xp.x, wE.x, u2[2*g][0]);                 \
                u2[2*g][1]   = ffma2(xp.x, wE.y, u2[2*g][1]);                 \
                u2[2*g][2]   = ffma2(xp.x, wK.x, u2[2*g][2]);                 \
                u2[2*g][3]   = ffma2(xp.x, wK.y, u2[2*g][3]);                 \
                u2[2*g+1][0] = ffma2(xp.y, wE.x, u2[2*g+1][0]);               \
                u2[2*g+1][1] = ffma2(xp.y, wE.y, u2[2*g+1][1]);               \
                u2[2*g+1][2] = ffma2(xp.y, wK.x, u2[2*g+1][2]);               \
                u2[2*g+1][3] = ffma2(xp.y, wK.y, u2[2*g+1][3]);               \
            }                                                                 \
        }                                                                     \
    }

    // prologue: front half for t=0 from buffer 0
    FRONT_HALF(xsP)

    for (int t = 0; t < T_; t++) {
        const int p = t & 1;
        const float* xsp = xsP + p * 336;
        float* xsn = xsP + (p ^ 1) * 336;

        // ---- back half: xi inputs k=12..17 (xi(t) visible in xsp) ----
        #pragma unroll
        for (int k = 12; k < 18; k++) {
            ulonglong2 wE = *(const ulonglong2*)(W1wE + k * 512);
            ulonglong2 wK = *(const ulonglong2*)(W1wK + k * 512);
            #pragma unroll
            for (int g = 0; g < 4; g++) {
                ulonglong2 xp = *(const ulonglong2*)(xsp + (k * 8 + 2 * g) * 2);
                u2[2*g][0]   = ffma2(xp.x, wE.x, u2[2*g][0]);
                u2[2*g][1]   = ffma2(xp.x, wE.y, u2[2*g][1]);
                u2[2*g][2]   = ffma2(xp.x, wK.x, u2[2*g][2]);
                u2[2*g][3]   = ffma2(xp.x, wK.y, u2[2*g][3]);
                u2[2*g+1][0] = ffma2(xp.y, wE.x, u2[2*g+1][0]);
                u2[2*g+1][1] = ffma2(xp.y, wE.y, u2[2*g+1][1]);
                u2[2*g+1][2] = ffma2(xp.y, wK.x, u2[2*g+1][2]);
                u2[2*g+1][3] = ffma2(xp.y, wK.y, u2[2*g+1][3]);
            }
        }
        #pragma unroll
        for (int r = 0; r < 8; r++) {
            u2[r][0] = relu2(u2[r][0]); u2[r][1] = relu2(u2[r][1]);
            u2[r][2] = relu2(u2[r][2]); u2[r][3] = relu2(u2[r][3]);
        }

        // ---- layer-2 partials: two groups of 4 rows (28 slots each), fold, STS ----
        #pragma unroll
        for (int g2 = 0; g2 < 2; g2++) {
            float v[32];
            #pragma unroll
            for (int rr = 0; rr < 4; rr++) {
                const int r = 4 * g2 + rr;
                #pragma unroll
                for (int j = 0; j < 6; j++) {
                    u64 a2 = ffma2(u2[r][2], wd2x[j].x, 0ULL);
                    a2 = ffma2(u2[r][3], wd2x[j].y, a2);
                    float2 q = unpk(a2);
                    v[rr * 7 + j] = q.x + q.y;
                }
                u64 s2 = ffma2(u2[r][0], wen2x.x, 0ULL);
                s2 = ffma2(u2[r][1], wen2x.y, s2);
                float2 q = unpk(s2);
                v[rr * 7 + 6] = q.x + q.y;
            }
            #pragma unroll
            for (int m = 28; m < 32; m++) v[m] = 0.f;
            fold32(v, lane);
            if (lane < 28) pP[pw * 56 + g2 * 28 + lane] = v[0];
        }

        // stage e/ed(t+1) into next buffer; prefetch e/ed(t+2)
        if (stager) {
            *(u64*)(xsn + (sj * 8 + sr) * 2)       = dup2(pe);
            *(u64*)(xsn + ((6 + sj) * 8 + sr) * 2) = dup2(ped);
            int tn = (t + 2 < T_) ? (t + 2) : (T_ - 1);
            pe  = e_[ebase + tn * 6];
            ped = ed_[ebase + tn * 6];
        }
        barpair(barId);

        // ---- owner combine: outputs + Euler + xi(t+1) into next buffer ----
        if (owner) {
            float val = pP[s_own] + pP[56 + s_own];
            if (jo < 6) {
                xi_ptr[t * 6] = xi_val;                  // emit xi BEFORE update
                xi_val = fmaf(DT_, val + bd2v, xi_val);
                *(u64*)(xsn + ((12 + jo) * 8 + ro) * 2) = dup2(xi_val);
            } else {
                s_ptr[t] = val + ben2r;
            }
        }

        // ---- front half of t+1 (independent of xi(t+1)) ----
        FRONT_HALF(xsn)

        barpair(barId);   // xi(t+1) now visible for next iteration's back half
    }
    #undef FRONT_HALF
}

extern "C" void kernel_launch(void* const* d_in, const int* in_sizes, int n_in,
                              void* d_out, int out_size) {
    (void)in_sizes; (void)n_in; (void)out_size;
    cudaFuncSetAttribute(visco_kernel,
                         cudaFuncAttributeMaxDynamicSharedMemorySize, SMEM_BYTES);
    visco_kernel<<<NBLK, THREADS, SMEM_BYTES>>>(
        (const float*)d_in[0],  (const float*)d_in[1],
        (const float*)d_in[2],  (const float*)d_in[3],
        (const float*)d_in[4],  (const float*)d_in[5],
        (const float*)d_in[6],  (const float*)d_in[7],
        (const float*)d_in[8],  (const float*)d_in[9],
        (const float*)d_in[10], (const float*)d_in[11],
        (const float*)d_in[12], (const float*)d_in[13],
        (const float*)d_in[14], (const float*)d_in[15],
        (float*)d_out);
}